// round 17
// baseline (speedup 1.0000x reference)
#include <cuda_runtime.h>
#include <cstdint>

// DCN cross network, collapsed algebra, persistent warps + double-buffered
// cp.async pipeline.
//   xi_{l+1} = x0*(xi_l . w_l) + b_l + xi_l
//   xi_l = a_l*x0 + sum_{m<l} b_m   (bias coefficients provably stay 1)
//   s_l = a_l*(x0.w_l) + sum_{m<l}(b_m.w_l);  a_{l+1} = a_l + s_l;  a_0 = 1
//   out = a_4*x0 + sum_m b_m
// Each warp owns a stream of rows. Row r+1 is cp.async'd into the alternate
// smem buffer while row r is computed -> every warp keeps 4 KB continuously
// in flight. Each lane reads only the smem bytes it copied itself, so the
// only sync is cp.async.wait_group. No barriers.

constexpr int D = 1024;
constexpr int THREADS = 256;           // 8 warps per CTA
constexpr int WARPS = THREADS / 32;
constexpr int CHUNKS = D / 128;        // 8 float4 per lane per row
constexpr int GRID = 444;              // 3 CTAs/SM x 148 SMs

__device__ float  g_k[3];              // {c01, c02+c12, c03+c13+c23}
__device__ float4 g_bsum4[D / 4];      // b0+b1+b2+b3 packed float4

__global__ __launch_bounds__(1024) void precompute_kernel(
    const float* __restrict__ w, const float* __restrict__ b)
{
    const int e = threadIdx.x;         // 0..1023
    const int lane = e & 31, warp = e >> 5;

    float w1 = w[D + e], w2 = w[2 * D + e], w3 = w[3 * D + e];
    float b0 = b[e], b1 = b[D + e], b2 = b[2 * D + e], b3 = b[3 * D + e];

    reinterpret_cast<float*>(g_bsum4)[e] = (b0 + b1) + (b2 + b3);

    // k0 = b0.w1 ; k1 = (b0+b1).w2 ; k2 = (b0+b1+b2).w3
    float p0 = b0 * w1;
    float p1 = (b0 + b1) * w2;
    float p2 = ((b0 + b1) + b2) * w3;

    __shared__ float red[32][3];
#pragma unroll
    for (int o = 16; o > 0; o >>= 1) {
        p0 += __shfl_xor_sync(0xffffffffu, p0, o);
        p1 += __shfl_xor_sync(0xffffffffu, p1, o);
        p2 += __shfl_xor_sync(0xffffffffu, p2, o);
    }
    if (lane == 0) { red[warp][0] = p0; red[warp][1] = p1; red[warp][2] = p2; }
    __syncthreads();

    if (warp == 0 && lane < 3) {
        float v = 0.f;
#pragma unroll
        for (int i = 0; i < 32; i++) v += red[i][lane];
        g_k[lane] = v;
    }
}

__device__ __forceinline__ uint32_t smem_u32(const void* p) {
    uint32_t a;
    asm("{ .reg .u64 t; cvta.to.shared.u64 t, %1; cvt.u32.u64 %0, t; }"
        : "=r"(a) : "l"(p));
    return a;
}

__global__ __launch_bounds__(THREADS) void cross_network_kernel(
    const float* __restrict__ x, const float* __restrict__ w,
    float* __restrict__ out, int batch, int total_warps)
{
    __shared__ float4 xtile[WARPS][2][D / 4];   // 8 warps x 2 bufs x 4 KB = 64 KB

    const int lane = threadIdx.x & 31;
    const int warp = threadIdx.x >> 5;
    const int gw = blockIdx.x * WARPS + warp;   // global warp id

    const float4* __restrict__ x4 = reinterpret_cast<const float4*>(x);
    const float4* __restrict__ w4 = reinterpret_cast<const float4*>(w);
    float4* __restrict__ o4 = reinterpret_cast<float4*>(out);

    const uint32_t sb0 = smem_u32(&xtile[warp][0][0]);
    const uint32_t sb1 = smem_u32(&xtile[warp][1][0]);

    // Prologue: prefetch first row into buffer 0.
    if (gw < batch) {
        const float4* src = x4 + (size_t)gw * (D / 4);
#pragma unroll
        for (int j = 0; j < CHUNKS; j++) {
            const int eoff = j * 32 + lane;
            asm volatile("cp.async.cg.shared.global [%0], [%1], 16;"
                         :: "r"(sb0 + eoff * 16), "l"(src + eoff));
        }
    }
    asm volatile("cp.async.commit_group;");

    const float c01 = g_k[0], k2 = g_k[1], k3 = g_k[2];

    int it = 0;
    for (int row = gw; row < batch; row += total_warps, it++) {
        // Prefetch next row into alternate buffer while computing this one.
        const int nrow = row + total_warps;
        const uint32_t nbuf = ((it + 1) & 1) ? sb1 : sb0;
        if (nrow < batch) {
            const float4* src = x4 + (size_t)nrow * (D / 4);
#pragma unroll
            for (int j = 0; j < CHUNKS; j++) {
                const int eoff = j * 32 + lane;
                asm volatile("cp.async.cg.shared.global [%0], [%1], 16;"
                             :: "r"(nbuf + eoff * 16), "l"(src + eoff));
            }
        }
        asm volatile("cp.async.commit_group;");
        // Wait until at most 1 group pending -> current row's buffer is ready,
        // next row's group stays in flight.
        asm volatile("cp.async.wait_group 1;" ::: "memory");

        const float4* xbuf = xtile[warp][it & 1];
        float4* __restrict__ orow = o4 + (size_t)row * (D / 4);

        // Partial dots for all 4 layers; x from smem, weights L1-hot LDG.
        float4 p = make_float4(0.f, 0.f, 0.f, 0.f);
#pragma unroll
        for (int j = 0; j < CHUNKS; j++) {
            const int eoff = j * 32 + lane;
            float4 xv = xbuf[eoff];
            float4 w0 = w4[0 * (D / 4) + eoff];
            float4 w1 = w4[1 * (D / 4) + eoff];
            float4 w2 = w4[2 * (D / 4) + eoff];
            float4 w3 = w4[3 * (D / 4) + eoff];
            p.x = fmaf(xv.x, w0.x, p.x); p.x = fmaf(xv.y, w0.y, p.x);
            p.x = fmaf(xv.z, w0.z, p.x); p.x = fmaf(xv.w, w0.w, p.x);
            p.y = fmaf(xv.x, w1.x, p.y); p.y = fmaf(xv.y, w1.y, p.y);
            p.y = fmaf(xv.z, w1.z, p.y); p.y = fmaf(xv.w, w1.w, p.y);
            p.z = fmaf(xv.x, w2.x, p.z); p.z = fmaf(xv.y, w2.y, p.z);
            p.z = fmaf(xv.z, w2.z, p.z); p.z = fmaf(xv.w, w2.w, p.z);
            p.w = fmaf(xv.x, w3.x, p.w); p.w = fmaf(xv.y, w3.y, p.w);
            p.w = fmaf(xv.z, w3.z, p.w); p.w = fmaf(xv.w, w3.w, p.w);
        }

        // One warp-shuffle reduction pass for all 4 dots.
#pragma unroll
        for (int o = 16; o > 0; o >>= 1) {
            p.x += __shfl_xor_sync(0xffffffffu, p.x, o);
            p.y += __shfl_xor_sync(0xffffffffu, p.y, o);
            p.z += __shfl_xor_sync(0xffffffffu, p.z, o);
            p.w += __shfl_xor_sync(0xffffffffu, p.w, o);
        }

        // Scalar recurrence (uniform across warp).
        float a = 1.f + p.x;                       // layer 0
        float s = fmaf(a, p.y, c01);  a += s;      // layer 1
        s = fmaf(a, p.z, k2);         a += s;      // layer 2
        s = fmaf(a, p.w, k3);         a += s;      // layer 3

        // Epilogue: out = a * x0 + bsum (x re-read from this lane's smem bytes).
#pragma unroll
        for (int j = 0; j < CHUNKS; j++) {
            const int eoff = j * 32 + lane;
            float4 xv = xbuf[eoff];
            float4 bsv = g_bsum4[eoff];
            float4 ov;
            ov.x = fmaf(a, xv.x, bsv.x);
            ov.y = fmaf(a, xv.y, bsv.y);
            ov.z = fmaf(a, xv.z, bsv.z);
            ov.w = fmaf(a, xv.w, bsv.w);
            orow[eoff] = ov;
        }
    }
}

extern "C" void kernel_launch(void* const* d_in, const int* in_sizes, int n_in,
                              void* d_out, int out_size)
{
    const float* x = (const float*)d_in[0];
    const float* w = (const float*)d_in[1];
    const float* b = (const float*)d_in[2];
    float* out = (float*)d_out;

    const int batch = in_sizes[0] / D;                 // 16384
    const int grid = (batch >= GRID * WARPS) ? GRID
                     : (batch + WARPS - 1) / WARPS;
    const int total_warps = grid * WARPS;

    precompute_kernel<<<1, 1024>>>(w, b);
    cross_network_kernel<<<grid, THREADS>>>(x, w, out, batch, total_warps);
}